// round 14
// baseline (speedup 1.0000x reference)
#include <cuda_runtime.h>
#include <cuda_bf16.h>

#define N_TOK    49
#define CDIM     128
#define NH       4
#define DH       32
#define QKV_N    384
#define NWIN     64
#define NTHREADS 512
#define NBLOCKS  152
#define SCALE    0.17677669529663687f

// ---- smem layout (bytes) ----
#define SM_QF_H   0          // Q A-frags hi / later ao A-frags (overlay)
#define SM_QF_L   16384
#define SM_KF4    32768      // K B-frags interleaved {h0,h1,l0,l1}
#define SM_VF4    65536      // V B-frags interleaved
#define SM_XFH    98304      // x A-frags hi
#define SM_XFL    114688     // x A-frags lo
#define SM_PW4    131072     // proj weights interleaved (resident whole block)
#define SM_XST    196608     // raw x staging for next window (25088 B)
#define SMEM_BYTES 221696

typedef unsigned long long u64;
typedef unsigned int u32;

// ---------------- device globals ----------------
__device__ float g_abias_frag[NWIN * NH * 4 * 8 * 32 * 4];  // [w][h][t][j][lane][q]
__device__ uint4 g_wqkv4[8 * 48 * 32];     // [k16][n8][lane] = {h0,h1,l0,l1}
__device__ uint4 g_wproj4[8 * 16 * 32];

// ---------------- helpers ----------------
__device__ __forceinline__ u64 pack2(float lo, float hi) {
    u64 r; asm("mov.b64 %0, {%1, %2};" : "=l"(r) : "f"(lo), "f"(hi)); return r;
}
__device__ __forceinline__ void unpack2(u64 v, float& lo, float& hi) {
    asm("mov.b64 {%0, %1}, %2;" : "=f"(lo), "=f"(hi) : "l"(v));
}
__device__ __forceinline__ void bsplit(float a, float b, u32& hi, u32& lo) {
    __nv_bfloat16 ah = __float2bfloat16(a), bh = __float2bfloat16(b);
    __nv_bfloat16 al = __float2bfloat16(a - __bfloat162float(ah));
    __nv_bfloat16 bl = __float2bfloat16(b - __bfloat162float(bh));
    hi = (u32)__bfloat16_as_ushort(ah) | ((u32)__bfloat16_as_ushort(bh) << 16);
    lo = (u32)__bfloat16_as_ushort(al) | ((u32)__bfloat16_as_ushort(bl) << 16);
}
__device__ __forceinline__ void mma_bf16(float c[4], const u32 a[4], const u32 b[2]) {
    asm volatile("mma.sync.aligned.m16n8k16.row.col.f32.bf16.bf16.f32 "
                 "{%0,%1,%2,%3}, {%4,%5,%6,%7}, {%8,%9}, {%0,%1,%2,%3};"
                 : "+f"(c[0]), "+f"(c[1]), "+f"(c[2]), "+f"(c[3])
                 : "r"(a[0]), "r"(a[1]), "r"(a[2]), "r"(a[3]), "r"(b[0]), "r"(b[1]));
}
__device__ __forceinline__ void cp16(u32 daddr, const void* src) {
    asm volatile("cp.async.cg.shared.global [%0], [%1], 16;" :: "r"(daddr), "l"(src));
}
__device__ __forceinline__ void cp_commit() { asm volatile("cp.async.commit_group;"); }
template <int N> __device__ __forceinline__ void cp_wait() {
    asm volatile("cp.async.wait_group %0;" :: "n"(N));
}

// ---------------- prep kernels ----------------
__global__ void build_abias_kernel(const float* __restrict__ mask,
                                   const float* __restrict__ bias_table,
                                   const int*   __restrict__ rel_index)
{
    int idx = blockIdx.x * blockDim.x + threadIdx.x;
    const int TOT = NWIN * NH * 4 * 8 * 32 * 4;
    if (idx >= TOT) return;
    int q    = idx & 3;
    int lane = (idx >> 2) & 31;
    int j    = (idx >> 7) & 7;
    int t    = (idx >> 10) & 3;
    int h    = (idx >> 12) & 3;
    int w    = idx >> 14;
    int g = lane >> 2, tig = lane & 3;
    int i = 16 * t + g + 8 * (q >> 1);
    int m = j * 8 + 2 * tig + (q & 1);
    float v;
    if (m >= N_TOK)      v = -1e9f;
    else if (i >= N_TOK) v = 0.f;
    else v = bias_table[rel_index[i * N_TOK + m] * NH + h]
           + mask[(w * N_TOK + i) * N_TOK + m];
    g_abias_frag[idx] = v;
}

__global__ void pack_w4_kernel(const float* __restrict__ W, uint4* d4,
                               int N, int nn8, int total)
{
    int s = blockIdx.x * blockDim.x + threadIdx.x;
    if (s >= total) return;
    int ln  = s & 31;
    int n8  = (s >> 5) % nn8;
    int k16 = s / (nn8 * 32);
    int gg = ln >> 2, tt = ln & 3;
    int col = n8 * 8 + gg;
    int r = k16 * 16 + 2 * tt;
    float w0 = W[(r + 0) * N + col], w1 = W[(r + 1) * N + col];
    float w2 = W[(r + 8) * N + col], w3 = W[(r + 9) * N + col];
    u32 h0, l0, h1, l1;
    bsplit(w0, w1, h0, l0);
    bsplit(w2, w3, h1, l1);
    d4[s] = make_uint4(h0, h1, l0, l1);
}

// ---------------- main kernel (persistent) ----------------
__global__ void __launch_bounds__(NTHREADS, 1)
win_attn_kernel(const float* __restrict__ x,
                const float* __restrict__ qkv_b,
                const float* __restrict__ proj_b,
                float* __restrict__ out,
                int B)
{
    extern __shared__ char smem[];
    const u32 smem_u32 = (u32)__cvta_generic_to_shared(smem);

    const int tid  = threadIdx.x;
    const int warp = tid >> 5;
    const int lane = tid & 31;
    const int g    = lane >> 2;
    const int tig  = lane & 3;

    const int mw = warp & 1;          // P2: rows mw*32..+31
    const int nw = warp >> 1;         // P2: cols nw*48..+47

    const int stride = gridDim.x;

    // ---- one-time: stage x for first window, then proj weights ----
    {
        const uint4* xs = (const uint4*)(x + (size_t)blockIdx.x * (N_TOK * CDIM));
        const u32 dX = smem_u32 + SM_XST;
        #pragma unroll
        for (int i = 0; i < 4; ++i) {
            const int idx = tid + i * NTHREADS;
            if (idx < 1568) cp16(dX + idx * 16, xs + idx);
        }
        cp_commit();
        const uint4* src4 = (const uint4*)g_wproj4;
        const u32 dPW = smem_u32 + SM_PW4;
        #pragma unroll
        for (int i = 0; i < 8; ++i) {
            const int idx = tid + i * NTHREADS;
            cp16(dPW + idx * 16, src4 + idx);
        }
        cp_commit();
    }

    for (int b = blockIdx.x; b < B; b += stride) {
        cp_wait<0>();
        __syncthreads();   // staged x visible; prev window's P4 reads of QF done

        // ---- prefetch first weight half-tile (k16=0, j=0..2) into registers ----
        u32 bh[2][3][2], bl[2][3][2];
        #pragma unroll
        for (int jj = 0; jj < 3; ++jj) {
            uint4 w4 = g_wqkv4[(nw * 6 + jj) * 32 + lane];
            bh[0][jj][0] = w4.x; bh[0][jj][1] = w4.y;
            bl[0][jj][0] = w4.z; bl[0][jj][1] = w4.w;
        }

        // ---- P0: pack staged x into A-fragments (bf16 hi/lo), rows >=49 zero ----
        {
            const float* xb = (const float*)(smem + SM_XST);
            u32* xfH = (u32*)(smem + SM_XFH);
            u32* xfL = (u32*)(smem + SM_XFL);
            #pragma unroll
            for (int it = 0; it < 2; ++it) {
                int s = tid + it * NTHREADS;
                int k16 = s >> 7, m16 = (s >> 5) & 3, ln = s & 31;
                int gg = ln >> 2, tt = ln & 3;
                int r0 = m16 * 16 + gg, r1 = r0 + 8;
                int c0 = k16 * 16 + 2 * tt;
                float2 p00 = (r0 < N_TOK) ? *(const float2*)&xb[r0 * CDIM + c0]     : make_float2(0.f, 0.f);
                float2 p10 = (r1 < N_TOK) ? *(const float2*)&xb[r1 * CDIM + c0]     : make_float2(0.f, 0.f);
                float2 p01 = (r0 < N_TOK) ? *(const float2*)&xb[r0 * CDIM + c0 + 8] : make_float2(0.f, 0.f);
                float2 p11 = (r1 < N_TOK) ? *(const float2*)&xb[r1 * CDIM + c0 + 8] : make_float2(0.f, 0.f);
                u32 h[4], l[4];
                bsplit(p00.x, p00.y, h[0], l[0]);
                bsplit(p10.x, p10.y, h[1], l[1]);
                bsplit(p01.x, p01.y, h[2], l[2]);
                bsplit(p11.x, p11.y, h[3], l[3]);
                *(uint4*)&xfH[s * 4] = make_uint4(h[0], h[1], h[2], h[3]);
                *(uint4*)&xfL[s * 4] = make_uint4(l[0], l[1], l[2], l[3]);
            }
        }
        __syncthreads();   // xstage consumed; XF ready

        // ---- prefetch next window's x into xstage (overlaps P2+P3+P4) ----
        if (b + stride < B) {
            const uint4* xs = (const uint4*)(x + (size_t)(b + stride) * (N_TOK * CDIM));
            const u32 dX = smem_u32 + SM_XST;
            #pragma unroll
            for (int i = 0; i < 4; ++i) {
                const int idx = tid + i * NTHREADS;
                if (idx < 1568) cp16(dX + idx * 16, xs + idx);
            }
            cp_commit();
        }

        // ---- P2: qkv GEMM, 16 warps, 32x48 tiles, weights L2->regs ----
        {
            const u32* xfH = (const u32*)(smem + SM_XFH);
            const u32* xfL = (const u32*)(smem + SM_XFL);

            float c[2][6][4];
            #pragma unroll
            for (int tp = 0; tp < 2; ++tp)
                #pragma unroll
                for (int j = 0; j < 6; ++j)
                    #pragma unroll
                    for (int q = 0; q < 4; ++q) c[tp][j][q] = 0.f;

            u32 aH[2][4], aL[2][4];

            #pragma unroll
            for (int s = 0; s < 16; ++s) {
                const int k16 = s >> 1;
                const int jh  = s & 1;
                const int cur = s & 1;
                const int nxt = cur ^ 1;

                if (s < 15) {
                    const int s2 = s + 1;
                    const int k16n = s2 >> 1, jhn = s2 & 1;
                    #pragma unroll
                    for (int jj = 0; jj < 3; ++jj) {
                        uint4 w4 = g_wqkv4[(k16n * 48 + nw * 6 + jhn * 3 + jj) * 32 + lane];
                        bh[nxt][jj][0] = w4.x; bh[nxt][jj][1] = w4.y;
                        bl[nxt][jj][0] = w4.z; bl[nxt][jj][1] = w4.w;
                    }
                }
                if (jh == 0) {
                    #pragma unroll
                    for (int tp = 0; tp < 2; ++tp) {
                        const int t = 2 * mw + tp;
                        uint4 vh = *(const uint4*)&xfH[((k16 * 4 + t) * 32 + lane) * 4];
                        uint4 vl = *(const uint4*)&xfL[((k16 * 4 + t) * 32 + lane) * 4];
                        aH[tp][0] = vh.x; aH[tp][1] = vh.y; aH[tp][2] = vh.z; aH[tp][3] = vh.w;
                        aL[tp][0] = vl.x; aL[tp][1] = vl.y; aL[tp][2] = vl.z; aL[tp][3] = vl.w;
                    }
                }
                #pragma unroll
                for (int tp = 0; tp < 2; ++tp) {
                    #pragma unroll
                    for (int jj = 0; jj < 3; ++jj) {
                        const int j = jh * 3 + jj;
                        mma_bf16(c[tp][j], aH[tp], bh[cur][jj]);
                        mma_bf16(c[tp][j], aH[tp], bl[cur][jj]);
                        mma_bf16(c[tp][j], aL[tp], bh[cur][jj]);
                    }
                }
            }

            // ---- epilogue: per-k16 region dispatch ----
            float bias0[6], bias1[6];
            #pragma unroll
            for (int j = 0; j < 6; ++j) {
                const int gcol = nw * 48 + j * 8 + 2 * tig;
                bias0[j] = qkv_b[gcol];
                bias1[j] = qkv_b[gcol + 1];
            }

            #pragma unroll
            for (int lk = 0; lk < 3; ++lk) {
                const int gk16 = nw * 3 + lk;
                const int j0 = 2 * lk, j1 = 2 * lk + 1;
                if (gk16 < 8) {
                    uint4* qfH = (uint4*)(smem + SM_QF_H);
                    uint4* qfL = (uint4*)(smem + SM_QF_L);
                    #pragma unroll
                    for (int tp = 0; tp < 2; ++tp) {
                        const int t = 2 * mw + tp;
                        float v0 = (c[tp][j0][0] + bias0[j0]) * SCALE;
                        float v1 = (c[tp][j0][1] + bias1[j0]) * SCALE;
                        float v2 = (c[tp][j0][2] + bias0[j0]) * SCALE;
                        float v3 = (c[tp][j0][3] + bias1[j0]) * SCALE;
                        float v4 = (c[tp][j1][0] + bias0[j1]) * SCALE;
                        float v5 = (c[tp][j1][1] + bias1[j1]) * SCALE;
                        float v6 = (c[tp][j1][2] + bias0[j1]) * SCALE;
                        float v7 = (c[tp][j1][3] + bias1[j1]) * SCALE;
                        u32 h0, l0, h1, l1, h2, l2, h3, l3;
                        bsplit(v0, v1, h0, l0);
                        bsplit(v2, v3, h1, l1);
                        bsplit(v4, v5, h2, l2);
                        bsplit(v6, v7, h3, l3);
                        const int off = (gk16 * 4 + t) * 32 + lane;
                        qfH[off] = make_uint4(h0, h1, h2, h3);
                        qfL[off] = make_uint4(l0, l1, l2, l3);
                    }
                } else if (gk16 < 16) {
                    const int kk16 = gk16 - 8;
                    uint4* kf4 = (uint4*)(smem + SM_KF4);
                    #pragma unroll
                    for (int tp = 0; tp < 2; ++tp) {
                        const int t = 2 * mw + tp;
                        u32 h00, l00, h01, l01, h10, l10, h11, l11;
                        bsplit(c[tp][j0][0] + bias0[j0], c[tp][j0][1] + bias1[j0], h00, l00);
                        bsplit(c[tp][j1][0] + bias0[j1], c[tp][j1][1] + bias1[j1], h01, l01);
                        bsplit(c[tp][j0][2] + bias0[j0], c[tp][j0][3] + bias1[j0], h10, l10);
                        bsplit(c[tp][j1][2] + bias0[j1], c[tp][j1][3] + bias1[j1], h11, l11);
                        kf4[(kk16 * 8 + 2 * t) * 32 + lane]     = make_uint4(h00, h01, l00, l01);
                        kf4[(kk16 * 8 + 2 * t + 1) * 32 + lane] = make_uint4(h10, h11, l10, l11);
                    }
                } else {
                    uint4* vf4 = (uint4*)(smem + SM_VF4);
                    #pragma unroll
                    for (int jj = 0; jj < 2; ++jj) {
                        const int j = 2 * lk + jj;
                        const int n8v = (gk16 - 16) * 2 + jj;
                        #pragma unroll
                        for (int tp = 0; tp < 2; ++tp) {
                            const int t = 2 * mw + tp;
                            float c0 = c[tp][j][0] + bias0[j];
                            float c1 = c[tp][j][1] + bias1[j];
                            float c2 = c[tp][j][2] + bias0[j];
                            float c3 = c[tp][j][3] + bias1[j];
                            u64 p01 = pack2(c0, c1), p23 = pack2(c2, c3);
                            u64 r01 = __shfl_xor_sync(0xffffffffu, p01, 4);
                            u64 r23 = __shfl_xor_sync(0xffffffffu, p23, 4);
                            if (!(g & 1)) {
                                float e0, e1, e2, e3;
                                unpack2(r01, e0, e1);
                                unpack2(r23, e2, e3);
                                u32 h00, l00, h01, l01, h10, l10, h11, l11;
                                bsplit(c0, e0, h00, l00);
                                bsplit(c2, e2, h01, l01);
                                bsplit(c1, e1, h10, l10);
                                bsplit(c3, e3, h11, l11);
                                const int kp2 = g >> 1;
                                const int base = (t * 16 + n8v) * 32;
                                vf4[base + (2 * tig) * 4 + kp2]     = make_uint4(h00, h01, l00, l01);
                                vf4[base + (2 * tig + 1) * 4 + kp2] = make_uint4(h10, h11, l10, l11);
                            }
                        }
                    }
                }
            }
        }
        __syncthreads();   // fragments ready

        // ---- P3: attention, 16 warps: warp = (head h, m16 tile t) ----
        {
            const int h = warp >> 2;
            const int t = warp & 3;

            // scores: initialize accumulators WITH bias fragments (hides bias LDG
            // under the mma sequence; removes the post-mma add chain).
            // Only 7 key tiles — keys 56..63 are pure padding.
            float s[7][4];
            {
                const int w = b & (NWIN - 1);
                const float4* ab = (const float4*)(g_abias_frag + (size_t)(w * NH + h) * 4096);
                #pragma unroll
                for (int j = 0; j < 7; ++j) {
                    float4 bb = ab[(t * 8 + j) * 32 + lane];
                    s[j][0] = bb.x; s[j][1] = bb.y;
                    s[j][2] = bb.z; s[j][3] = bb.w;
                }
            }

            u32 qh[2][4], ql[2][4];
            {
                const uint4* qfH = (const uint4*)(smem + SM_QF_H);
                const uint4* qfL = (const uint4*)(smem + SM_QF_L);
                #pragma unroll
                for (int kk = 0; kk < 2; ++kk) {
                    const int off = ((2 * h + kk) * 4 + t) * 32 + lane;
                    uint4 vh = qfH[off], vl = qfL[off];
                    qh[kk][0] = vh.x; qh[kk][1] = vh.y; qh[kk][2] = vh.z; qh[kk][3] = vh.w;
                    ql[kk][0] = vl.x; ql[kk][1] = vl.y; ql[kk][2] = vl.z; ql[kk][3] = vl.w;
                }
            }

            {
                const uint4* kf4 = (const uint4*)(smem + SM_KF4);
                #pragma unroll
                for (int kk = 0; kk < 2; ++kk) {
                    #pragma unroll
                    for (int j = 0; j < 7; ++j) {
                        uint4 kv = kf4[((2 * h + kk) * 8 + j) * 32 + lane];
                        u32 bH[2] = {kv.x, kv.y};
                        u32 bL[2] = {kv.z, kv.w};
                        mma_bf16(s[j], qh[kk], bH);
                        mma_bf16(s[j], qh[kk], bL);
                        mma_bf16(s[j], ql[kk], bH);
                    }
                }
            }

            // softmax (immediate normalization)
            float inv[2];
            #pragma unroll
            for (int rh = 0; rh < 2; ++rh) {
                float mx = -1e30f;
                #pragma unroll
                for (int j = 0; j < 7; ++j) {
                    mx = fmaxf(mx, s[j][2 * rh]);
                    mx = fmaxf(mx, s[j][2 * rh + 1]);
                }
                mx = fmaxf(mx, __shfl_xor_sync(0xffffffffu, mx, 1));
                mx = fmaxf(mx, __shfl_xor_sync(0xffffffffu, mx, 2));
                float sum = 0.f;
                #pragma unroll
                for (int j = 0; j < 7; ++j) {
                    float e0 = __expf(s[j][2 * rh] - mx);
                    float e1 = __expf(s[j][2 * rh + 1] - mx);
                    s[j][2 * rh] = e0;
                    s[j][2 * rh + 1] = e1;
                    sum += e0 + e1;
                }
                sum += __shfl_xor_sync(0xffffffffu, sum, 1);
                sum += __shfl_xor_sync(0xffffffffu, sum, 2);
                inv[rh] = 1.f / sum;
            }

            // P -> A-frags (normalized); kk=3 upper regs (keys 56-63) = 0
            u32 ph[4][4], pl[4][4];
            #pragma unroll
            for (int kk = 0; kk < 3; ++kk) {
                bsplit(s[2 * kk][0] * inv[0], s[2 * kk][1] * inv[0], ph[kk][0], pl[kk][0]);
                bsplit(s[2 * kk][2] * inv[1], s[2 * kk][3] * inv[1], ph[kk][1], pl[kk][1]);
                bsplit(s[2 * kk + 1][0] * inv[0], s[2 * kk + 1][1] * inv[0], ph[kk][2], pl[kk][2]);
                bsplit(s[2 * kk + 1][2] * inv[1], s[2 * kk + 1][3] * inv[1], ph[kk][3], pl[kk][3]);
            }
            bsplit(s[6][0] * inv[0], s[6][1] * inv[0], ph[3][0], pl[3][0]);
            bsplit(s[6][2] * inv[1], s[6][3] * inv[1], ph[3][1], pl[3][1]);
            ph[3][2] = 0u; pl[3][2] = 0u;
            ph[3][3] = 0u; pl[3][3] = 0u;

            // PV
            float o[4][4];
            #pragma unroll
            for (int jd = 0; jd < 4; ++jd)
                #pragma unroll
                for (int q = 0; q < 4; ++q) o[jd][q] = 0.f;
            {
                const uint4* vf4 = (const uint4*)(smem + SM_VF4);
                #pragma unroll
                for (int kk = 0; kk < 4; ++kk) {
                    #pragma unroll
                    for (int jd = 0; jd < 4; ++jd) {
                        uint4 vv = vf4[(kk * 16 + 4 * h + jd) * 32 + lane];
                        u32 bH[2] = {vv.x, vv.y};
                        u32 bL[2] = {vv.z, vv.w};
                        mma_bf16(o[jd], ph[kk], bH);
                        mma_bf16(o[jd], ph[kk], bL);
                        mma_bf16(o[jd], pl[kk], bH);
                    }
                }
            }

            {
                uint4* aoH = (uint4*)(smem + SM_QF_H);
                uint4* aoL = (uint4*)(smem + SM_QF_L);
                #pragma unroll
                for (int kd = 0; kd < 2; ++kd) {
                    u32 h0, l0, h1, l1, h2, l2, h3, l3;
                    bsplit(o[2 * kd][0], o[2 * kd][1], h0, l0);
                    bsplit(o[2 * kd][2], o[2 * kd][3], h1, l1);
                    bsplit(o[2 * kd + 1][0], o[2 * kd + 1][1], h2, l2);
                    bsplit(o[2 * kd + 1][2], o[2 * kd + 1][3], h3, l3);
                    const int off = ((2 * h + kd) * 4 + t) * 32 + lane;
                    aoH[off] = make_uint4(h0, h1, h2, h3);
                    aoL[off] = make_uint4(l0, l1, l2, l3);
                }
            }
        }
        __syncthreads();   // ao ready

        // ---- P4: proj, 16 warps: warp = (m16 tile mw2, 32-col group nw2) ----
        {
            const int mw2 = warp & 3;
            const int nw2 = warp >> 2;
            const u32* aoH = (const u32*)(smem + SM_QF_H);
            const u32* aoL = (const u32*)(smem + SM_QF_L);
            const uint4* pw4 = (const uint4*)(smem + SM_PW4);

            float c[4][4];
            #pragma unroll
            for (int j = 0; j < 4; ++j)
                #pragma unroll
                for (int q = 0; q < 4; ++q) c[j][q] = 0.f;

            #pragma unroll
            for (int k16 = 0; k16 < 8; ++k16) {
                u32 aH[4], aL[4];
                uint4 vh = *(const uint4*)&aoH[((k16 * 4 + mw2) * 32 + lane) * 4];
                uint4 vl = *(const uint4*)&aoL[((k16 * 4 + mw2) * 32 + lane) * 4];
                aH[0] = vh.x; aH[1] = vh.y; aH[2] = vh.z; aH[3] = vh.w;
                aL[0] = vl.x; aL[1] = vl.y; aL[2] = vl.z; aL[3] = vl.w;
                #pragma unroll
                for (int j = 0; j < 4; ++j) {
                    uint4 wv = pw4[(k16 * 16 + nw2 * 4 + j) * 32 + lane];
                    u32 bH[2] = {wv.x, wv.y};
                    u32 bL[2] = {wv.z, wv.w};
                    mma_bf16(c[j], aH, bH);
                    mma_bf16(c[j], aH, bL);
                    mma_bf16(c[j], aL, bH);
                }
            }

            float* ob = out + (size_t)b * (N_TOK * CDIM);
            const int r0 = mw2 * 16 + g;
            const int r1 = r0 + 8;
            #pragma unroll
            for (int j = 0; j < 4; ++j) {
                const int col = nw2 * 32 + j * 8 + 2 * tig;
                const float b0 = proj_b[col], b1 = proj_b[col + 1];
                if (r0 < N_TOK)
                    *(float2*)&ob[r0 * CDIM + col] = make_float2(c[j][0] + b0, c[j][1] + b1);
                if (r1 < N_TOK)
                    *(float2*)&ob[r1 * CDIM + col] = make_float2(c[j][2] + b0, c[j][3] + b1);
            }
        }
    }
}

extern "C" void kernel_launch(void* const* d_in, const int* in_sizes, int n_in,
                              void* d_out, int out_size)
{
    const float* x          = (const float*)d_in[0];
    const float* mask       = (const float*)d_in[1];
    const float* qkv_w      = (const float*)d_in[2];
    const float* qkv_b      = (const float*)d_in[3];
    const float* proj_w     = (const float*)d_in[4];
    const float* proj_b     = (const float*)d_in[5];
    const float* bias_table = (const float*)d_in[6];
    const int*   rel_index  = (const int*)d_in[7];
    float* out = (float*)d_out;

    const int B = in_sizes[0] / (N_TOK * CDIM);

    {
        const int TOT = NWIN * NH * 4 * 8 * 32 * 4;
        build_abias_kernel<<<(TOT + 255) / 256, 256>>>(mask, bias_table, rel_index);
    }
    {
        uint4* d4;
        cudaGetSymbolAddress((void**)&d4, g_wqkv4);
        pack_w4_kernel<<<(8 * 48 * 32 + 255) / 256, 256>>>(qkv_w, d4, QKV_N, 48, 8 * 48 * 32);
        cudaGetSymbolAddress((void**)&d4, g_wproj4);
        pack_w4_kernel<<<(8 * 16 * 32 + 255) / 256, 256>>>(proj_w, d4, CDIM, 16, 8 * 16 * 32);
    }

    const int grid = (B < NBLOCKS) ? B : NBLOCKS;
    cudaFuncSetAttribute(win_attn_kernel,
                         cudaFuncAttributeMaxDynamicSharedMemorySize, SMEM_BYTES);
    win_attn_kernel<<<grid, NTHREADS, SMEM_BYTES>>>(x, qkv_b, proj_b, out, B);
}

// round 16
// speedup vs baseline: 1.1364x; 1.1364x over previous
#include <cuda_runtime.h>
#include <cuda_bf16.h>

#define N_TOK    49
#define CDIM     128
#define NH       4
#define DH       32
#define QKV_N    384
#define NWIN     64
#define NTHREADS 512
#define NBLOCKS  152
#define SCALE    0.17677669529663687f

// ---- smem layout (bytes) ----
#define SM_QF_H   0          // Q A-frags hi / later ao A-frags (overlay)
#define SM_QF_L   16384
#define SM_KF4    32768      // K B-frags interleaved {h0,h1,l0,l1}
#define SM_VF4    65536      // V B-frags interleaved
#define SM_XFH    98304      // x A-frags hi
#define SM_XFL    114688     // x A-frags lo
#define SM_PW4    131072     // proj weights interleaved (resident whole block)
#define SM_XST    196608     // raw x staging for next window (25088 B)
#define SMEM_BYTES 221696

typedef unsigned long long u64;
typedef unsigned int u32;

// ---------------- device globals ----------------
__device__ float g_abias_frag[NWIN * NH * 4 * 8 * 32 * 4];  // [w][h][t][j][lane][q]
__device__ uint4 g_wqkv4[8 * 48 * 32];     // [k16][n8][lane] = {h0,h1,l0,l1}
__device__ uint4 g_wproj4[8 * 16 * 32];

// ---------------- helpers ----------------
__device__ __forceinline__ u64 pack2(float lo, float hi) {
    u64 r; asm("mov.b64 %0, {%1, %2};" : "=l"(r) : "f"(lo), "f"(hi)); return r;
}
__device__ __forceinline__ void unpack2(u64 v, float& lo, float& hi) {
    asm("mov.b64 {%0, %1}, %2;" : "=f"(lo), "=f"(hi) : "l"(v));
}
// packed bf16x2 convert: result.lo = bf16(a), result.hi = bf16(b), round-to-nearest-even
__device__ __forceinline__ u32 cvt2(float a, float b) {
    u32 r; asm("cvt.rn.bf16x2.f32 %0, %1, %2;" : "=r"(r) : "f"(b), "f"(a)); return r;
}
// bf16 hi/lo split of pair (a,b) — bit-identical to scalar __float2bfloat16 path,
// but ~6 SASS ops via packed cvt + exact shift/mask bf16->f32 reconstruction.
__device__ __forceinline__ void bsplit(float a, float b, u32& hi, u32& lo) {
    hi = cvt2(a, b);
    float af = __uint_as_float(hi << 16);          // exact float(bf16(a))
    float bf = __uint_as_float(hi & 0xffff0000u);  // exact float(bf16(b))
    lo = cvt2(a - af, b - bf);
}
__device__ __forceinline__ void mma_bf16(float c[4], const u32 a[4], const u32 b[2]) {
    asm volatile("mma.sync.aligned.m16n8k16.row.col.f32.bf16.bf16.f32 "
                 "{%0,%1,%2,%3}, {%4,%5,%6,%7}, {%8,%9}, {%0,%1,%2,%3};"
                 : "+f"(c[0]), "+f"(c[1]), "+f"(c[2]), "+f"(c[3])
                 : "r"(a[0]), "r"(a[1]), "r"(a[2]), "r"(a[3]), "r"(b[0]), "r"(b[1]));
}
__device__ __forceinline__ void cp16(u32 daddr, const void* src) {
    asm volatile("cp.async.cg.shared.global [%0], [%1], 16;" :: "r"(daddr), "l"(src));
}
__device__ __forceinline__ void cp_commit() { asm volatile("cp.async.commit_group;"); }
template <int N> __device__ __forceinline__ void cp_wait() {
    asm volatile("cp.async.wait_group %0;" :: "n"(N));
}

// ---------------- prep kernels ----------------
__global__ void build_abias_kernel(const float* __restrict__ mask,
                                   const float* __restrict__ bias_table,
                                   const int*   __restrict__ rel_index)
{
    int idx = blockIdx.x * blockDim.x + threadIdx.x;
    const int TOT = NWIN * NH * 4 * 8 * 32 * 4;
    if (idx >= TOT) return;
    int q    = idx & 3;
    int lane = (idx >> 2) & 31;
    int j    = (idx >> 7) & 7;
    int t    = (idx >> 10) & 3;
    int h    = (idx >> 12) & 3;
    int w    = idx >> 14;
    int g = lane >> 2, tig = lane & 3;
    int i = 16 * t + g + 8 * (q >> 1);
    int m = j * 8 + 2 * tig + (q & 1);
    float v;
    if (m >= N_TOK)      v = -1e9f;
    else if (i >= N_TOK) v = 0.f;
    else v = bias_table[rel_index[i * N_TOK + m] * NH + h]
           + mask[(w * N_TOK + i) * N_TOK + m];
    g_abias_frag[idx] = v;
}

__global__ void pack_w4_kernel(const float* __restrict__ W, uint4* d4,
                               int N, int nn8, int total)
{
    int s = blockIdx.x * blockDim.x + threadIdx.x;
    if (s >= total) return;
    int ln  = s & 31;
    int n8  = (s >> 5) % nn8;
    int k16 = s / (nn8 * 32);
    int gg = ln >> 2, tt = ln & 3;
    int col = n8 * 8 + gg;
    int r = k16 * 16 + 2 * tt;
    float w0 = W[(r + 0) * N + col], w1 = W[(r + 1) * N + col];
    float w2 = W[(r + 8) * N + col], w3 = W[(r + 9) * N + col];
    u32 h0, l0, h1, l1;
    bsplit(w0, w1, h0, l0);
    bsplit(w2, w3, h1, l1);
    d4[s] = make_uint4(h0, h1, l0, l1);
}

// ---------------- main kernel (persistent) ----------------
__global__ void __launch_bounds__(NTHREADS, 1)
win_attn_kernel(const float* __restrict__ x,
                const float* __restrict__ qkv_b,
                const float* __restrict__ proj_b,
                float* __restrict__ out,
                int B)
{
    extern __shared__ char smem[];
    const u32 smem_u32 = (u32)__cvta_generic_to_shared(smem);

    const int tid  = threadIdx.x;
    const int warp = tid >> 5;
    const int lane = tid & 31;
    const int g    = lane >> 2;
    const int tig  = lane & 3;

    const int mw = warp & 1;          // P2: rows mw*32..+31
    const int nw = warp >> 1;         // P2: cols nw*48..+47

    const int stride = gridDim.x;

    // ---- one-time: stage x for first window, then proj weights ----
    {
        const uint4* xs = (const uint4*)(x + (size_t)blockIdx.x * (N_TOK * CDIM));
        const u32 dX = smem_u32 + SM_XST;
        #pragma unroll
        for (int i = 0; i < 4; ++i) {
            const int idx = tid + i * NTHREADS;
            if (idx < 1568) cp16(dX + idx * 16, xs + idx);
        }
        cp_commit();
        const uint4* src4 = (const uint4*)g_wproj4;
        const u32 dPW = smem_u32 + SM_PW4;
        #pragma unroll
        for (int i = 0; i < 8; ++i) {
            const int idx = tid + i * NTHREADS;
            cp16(dPW + idx * 16, src4 + idx);
        }
        cp_commit();
    }

    for (int b = blockIdx.x; b < B; b += stride) {
        cp_wait<0>();
        __syncthreads();   // staged x visible; prev window's P4 reads of QF done

        // ---- prefetch first weight half-tile (k16=0, j=0..2) into registers ----
        u32 bh[2][3][2], bl[2][3][2];
        #pragma unroll
        for (int jj = 0; jj < 3; ++jj) {
            uint4 w4 = g_wqkv4[(nw * 6 + jj) * 32 + lane];
            bh[0][jj][0] = w4.x; bh[0][jj][1] = w4.y;
            bl[0][jj][0] = w4.z; bl[0][jj][1] = w4.w;
        }

        // ---- P0: pack staged x into A-fragments (bf16 hi/lo), rows >=49 zero ----
        {
            const float* xb = (const float*)(smem + SM_XST);
            u32* xfH = (u32*)(smem + SM_XFH);
            u32* xfL = (u32*)(smem + SM_XFL);
            #pragma unroll
            for (int it = 0; it < 2; ++it) {
                int s = tid + it * NTHREADS;
                int k16 = s >> 7, m16 = (s >> 5) & 3, ln = s & 31;
                int gg = ln >> 2, tt = ln & 3;
                int r0 = m16 * 16 + gg, r1 = r0 + 8;
                int c0 = k16 * 16 + 2 * tt;
                float2 p00 = (r0 < N_TOK) ? *(const float2*)&xb[r0 * CDIM + c0]     : make_float2(0.f, 0.f);
                float2 p10 = (r1 < N_TOK) ? *(const float2*)&xb[r1 * CDIM + c0]     : make_float2(0.f, 0.f);
                float2 p01 = (r0 < N_TOK) ? *(const float2*)&xb[r0 * CDIM + c0 + 8] : make_float2(0.f, 0.f);
                float2 p11 = (r1 < N_TOK) ? *(const float2*)&xb[r1 * CDIM + c0 + 8] : make_float2(0.f, 0.f);
                u32 h[4], l[4];
                bsplit(p00.x, p00.y, h[0], l[0]);
                bsplit(p10.x, p10.y, h[1], l[1]);
                bsplit(p01.x, p01.y, h[2], l[2]);
                bsplit(p11.x, p11.y, h[3], l[3]);
                *(uint4*)&xfH[s * 4] = make_uint4(h[0], h[1], h[2], h[3]);
                *(uint4*)&xfL[s * 4] = make_uint4(l[0], l[1], l[2], l[3]);
            }
        }
        __syncthreads();   // xstage consumed; XF ready

        // ---- prefetch next window's x into xstage (overlaps P2+P3+P4) ----
        if (b + stride < B) {
            const uint4* xs = (const uint4*)(x + (size_t)(b + stride) * (N_TOK * CDIM));
            const u32 dX = smem_u32 + SM_XST;
            #pragma unroll
            for (int i = 0; i < 4; ++i) {
                const int idx = tid + i * NTHREADS;
                if (idx < 1568) cp16(dX + idx * 16, xs + idx);
            }
            cp_commit();
        }

        // ---- P2: qkv GEMM, 16 warps, 32x48 tiles, weights L2->regs ----
        {
            const u32* xfH = (const u32*)(smem + SM_XFH);
            const u32* xfL = (const u32*)(smem + SM_XFL);

            float c[2][6][4];
            #pragma unroll
            for (int tp = 0; tp < 2; ++tp)
                #pragma unroll
                for (int j = 0; j < 6; ++j)
                    #pragma unroll
                    for (int q = 0; q < 4; ++q) c[tp][j][q] = 0.f;

            u32 aH[2][4], aL[2][4];

            #pragma unroll
            for (int s = 0; s < 16; ++s) {
                const int k16 = s >> 1;
                const int jh  = s & 1;
                const int cur = s & 1;
                const int nxt = cur ^ 1;

                if (s < 15) {
                    const int s2 = s + 1;
                    const int k16n = s2 >> 1, jhn = s2 & 1;
                    #pragma unroll
                    for (int jj = 0; jj < 3; ++jj) {
                        uint4 w4 = g_wqkv4[(k16n * 48 + nw * 6 + jhn * 3 + jj) * 32 + lane];
                        bh[nxt][jj][0] = w4.x; bh[nxt][jj][1] = w4.y;
                        bl[nxt][jj][0] = w4.z; bl[nxt][jj][1] = w4.w;
                    }
                }
                if (jh == 0) {
                    #pragma unroll
                    for (int tp = 0; tp < 2; ++tp) {
                        const int t = 2 * mw + tp;
                        uint4 vh = *(const uint4*)&xfH[((k16 * 4 + t) * 32 + lane) * 4];
                        uint4 vl = *(const uint4*)&xfL[((k16 * 4 + t) * 32 + lane) * 4];
                        aH[tp][0] = vh.x; aH[tp][1] = vh.y; aH[tp][2] = vh.z; aH[tp][3] = vh.w;
                        aL[tp][0] = vl.x; aL[tp][1] = vl.y; aL[tp][2] = vl.z; aL[tp][3] = vl.w;
                    }
                }
                #pragma unroll
                for (int tp = 0; tp < 2; ++tp) {
                    #pragma unroll
                    for (int jj = 0; jj < 3; ++jj) {
                        const int j = jh * 3 + jj;
                        mma_bf16(c[tp][j], aH[tp], bh[cur][jj]);
                        mma_bf16(c[tp][j], aH[tp], bl[cur][jj]);
                        mma_bf16(c[tp][j], aL[tp], bh[cur][jj]);
                    }
                }
            }

            // ---- epilogue: per-k16 region dispatch ----
            float bias0[6], bias1[6];
            #pragma unroll
            for (int j = 0; j < 6; ++j) {
                const int gcol = nw * 48 + j * 8 + 2 * tig;
                bias0[j] = qkv_b[gcol];
                bias1[j] = qkv_b[gcol + 1];
            }

            #pragma unroll
            for (int lk = 0; lk < 3; ++lk) {
                const int gk16 = nw * 3 + lk;
                const int j0 = 2 * lk, j1 = 2 * lk + 1;
                if (gk16 < 8) {
                    uint4* qfH = (uint4*)(smem + SM_QF_H);
                    uint4* qfL = (uint4*)(smem + SM_QF_L);
                    #pragma unroll
                    for (int tp = 0; tp < 2; ++tp) {
                        const int t = 2 * mw + tp;
                        float v0 = (c[tp][j0][0] + bias0[j0]) * SCALE;
                        float v1 = (c[tp][j0][1] + bias1[j0]) * SCALE;
                        float v2 = (c[tp][j0][2] + bias0[j0]) * SCALE;
                        float v3 = (c[tp][j0][3] + bias1[j0]) * SCALE;
                        float v4 = (c[tp][j1][0] + bias0[j1]) * SCALE;
                        float v5 = (c[tp][j1][1] + bias1[j1]) * SCALE;
                        float v6 = (c[tp][j1][2] + bias0[j1]) * SCALE;
                        float v7 = (c[tp][j1][3] + bias1[j1]) * SCALE;
                        u32 h0, l0, h1, l1, h2, l2, h3, l3;
                        bsplit(v0, v1, h0, l0);
                        bsplit(v2, v3, h1, l1);
                        bsplit(v4, v5, h2, l2);
                        bsplit(v6, v7, h3, l3);
                        const int off = (gk16 * 4 + t) * 32 + lane;
                        qfH[off] = make_uint4(h0, h1, h2, h3);
                        qfL[off] = make_uint4(l0, l1, l2, l3);
                    }
                } else if (gk16 < 16) {
                    const int kk16 = gk16 - 8;
                    uint4* kf4 = (uint4*)(smem + SM_KF4);
                    #pragma unroll
                    for (int tp = 0; tp < 2; ++tp) {
                        const int t = 2 * mw + tp;
                        u32 h00, l00, h01, l01, h10, l10, h11, l11;
                        bsplit(c[tp][j0][0] + bias0[j0], c[tp][j0][1] + bias1[j0], h00, l00);
                        bsplit(c[tp][j1][0] + bias0[j1], c[tp][j1][1] + bias1[j1], h01, l01);
                        bsplit(c[tp][j0][2] + bias0[j0], c[tp][j0][3] + bias1[j0], h10, l10);
                        bsplit(c[tp][j1][2] + bias0[j1], c[tp][j1][3] + bias1[j1], h11, l11);
                        kf4[(kk16 * 8 + 2 * t) * 32 + lane]     = make_uint4(h00, h01, l00, l01);
                        kf4[(kk16 * 8 + 2 * t + 1) * 32 + lane] = make_uint4(h10, h11, l10, l11);
                    }
                } else {
                    uint4* vf4 = (uint4*)(smem + SM_VF4);
                    #pragma unroll
                    for (int jj = 0; jj < 2; ++jj) {
                        const int j = 2 * lk + jj;
                        const int n8v = (gk16 - 16) * 2 + jj;
                        #pragma unroll
                        for (int tp = 0; tp < 2; ++tp) {
                            const int t = 2 * mw + tp;
                            float c0 = c[tp][j][0] + bias0[j];
                            float c1 = c[tp][j][1] + bias1[j];
                            float c2 = c[tp][j][2] + bias0[j];
                            float c3 = c[tp][j][3] + bias1[j];
                            u64 p01 = pack2(c0, c1), p23 = pack2(c2, c3);
                            u64 r01 = __shfl_xor_sync(0xffffffffu, p01, 4);
                            u64 r23 = __shfl_xor_sync(0xffffffffu, p23, 4);
                            if (!(g & 1)) {
                                float e0, e1, e2, e3;
                                unpack2(r01, e0, e1);
                                unpack2(r23, e2, e3);
                                u32 h00, l00, h01, l01, h10, l10, h11, l11;
                                bsplit(c0, e0, h00, l00);
                                bsplit(c2, e2, h01, l01);
                                bsplit(c1, e1, h10, l10);
                                bsplit(c3, e3, h11, l11);
                                const int kp2 = g >> 1;
                                const int base = (t * 16 + n8v) * 32;
                                vf4[base + (2 * tig) * 4 + kp2]     = make_uint4(h00, h01, l00, l01);
                                vf4[base + (2 * tig + 1) * 4 + kp2] = make_uint4(h10, h11, l10, l11);
                            }
                        }
                    }
                }
            }
        }
        __syncthreads();   // fragments ready

        // ---- P3: attention, 16 warps: warp = (head h, m16 tile t) ----
        {
            const int h = warp >> 2;
            const int t = warp & 3;

            u32 qh[2][4], ql[2][4];
            {
                const uint4* qfH = (const uint4*)(smem + SM_QF_H);
                const uint4* qfL = (const uint4*)(smem + SM_QF_L);
                #pragma unroll
                for (int kk = 0; kk < 2; ++kk) {
                    const int off = ((2 * h + kk) * 4 + t) * 32 + lane;
                    uint4 vh = qfH[off], vl = qfL[off];
                    qh[kk][0] = vh.x; qh[kk][1] = vh.y; qh[kk][2] = vh.z; qh[kk][3] = vh.w;
                    ql[kk][0] = vl.x; ql[kk][1] = vl.y; ql[kk][2] = vl.z; ql[kk][3] = vl.w;
                }
            }

            float s[8][4];
            #pragma unroll
            for (int j = 0; j < 8; ++j)
                #pragma unroll
                for (int q = 0; q < 4; ++q) s[j][q] = 0.f;
            {
                const uint4* kf4 = (const uint4*)(smem + SM_KF4);
                #pragma unroll
                for (int kk = 0; kk < 2; ++kk) {
                    #pragma unroll
                    for (int j = 0; j < 8; ++j) {
                        uint4 kv = kf4[((2 * h + kk) * 8 + j) * 32 + lane];
                        u32 bH[2] = {kv.x, kv.y};
                        u32 bL[2] = {kv.z, kv.w};
                        mma_bf16(s[j], qh[kk], bH);
                        mma_bf16(s[j], qh[kk], bL);
                        mma_bf16(s[j], ql[kk], bH);
                    }
                }
            }

            {
                const int w = b & (NWIN - 1);
                const float4* ab = (const float4*)(g_abias_frag + (size_t)(w * NH + h) * 4096);
                #pragma unroll
                for (int j = 0; j < 8; ++j) {
                    float4 bb = ab[(t * 8 + j) * 32 + lane];
                    s[j][0] += bb.x; s[j][1] += bb.y;
                    s[j][2] += bb.z; s[j][3] += bb.w;
                }
            }

            float inv[2];
            #pragma unroll
            for (int rh = 0; rh < 2; ++rh) {
                float mx = -1e30f;
                #pragma unroll
                for (int j = 0; j < 8; ++j) {
                    mx = fmaxf(mx, s[j][2 * rh]);
                    mx = fmaxf(mx, s[j][2 * rh + 1]);
                }
                mx = fmaxf(mx, __shfl_xor_sync(0xffffffffu, mx, 1));
                mx = fmaxf(mx, __shfl_xor_sync(0xffffffffu, mx, 2));
                float sum = 0.f;
                #pragma unroll
                for (int j = 0; j < 8; ++j) {
                    float e0 = __expf(s[j][2 * rh] - mx);
                    float e1 = __expf(s[j][2 * rh + 1] - mx);
                    s[j][2 * rh] = e0;
                    s[j][2 * rh + 1] = e1;
                    sum += e0 + e1;
                }
                sum += __shfl_xor_sync(0xffffffffu, sum, 1);
                sum += __shfl_xor_sync(0xffffffffu, sum, 2);
                inv[rh] = 1.f / sum;
            }

            u32 ph[4][4], pl[4][4];
            #pragma unroll
            for (int kk = 0; kk < 4; ++kk) {
                bsplit(s[2 * kk][0] * inv[0], s[2 * kk][1] * inv[0], ph[kk][0], pl[kk][0]);
                bsplit(s[2 * kk][2] * inv[1], s[2 * kk][3] * inv[1], ph[kk][1], pl[kk][1]);
                bsplit(s[2 * kk + 1][0] * inv[0], s[2 * kk + 1][1] * inv[0], ph[kk][2], pl[kk][2]);
                bsplit(s[2 * kk + 1][2] * inv[1], s[2 * kk + 1][3] * inv[1], ph[kk][3], pl[kk][3]);
            }

            float o[4][4];
            #pragma unroll
            for (int jd = 0; jd < 4; ++jd)
                #pragma unroll
                for (int q = 0; q < 4; ++q) o[jd][q] = 0.f;
            {
                const uint4* vf4 = (const uint4*)(smem + SM_VF4);
                #pragma unroll
                for (int kk = 0; kk < 4; ++kk) {
                    #pragma unroll
                    for (int jd = 0; jd < 4; ++jd) {
                        uint4 vv = vf4[(kk * 16 + 4 * h + jd) * 32 + lane];
                        u32 bH[2] = {vv.x, vv.y};
                        u32 bL[2] = {vv.z, vv.w};
                        mma_bf16(o[jd], ph[kk], bH);
                        mma_bf16(o[jd], ph[kk], bL);
                        mma_bf16(o[jd], pl[kk], bH);
                    }
                }
            }

            {
                uint4* aoH = (uint4*)(smem + SM_QF_H);
                uint4* aoL = (uint4*)(smem + SM_QF_L);
                #pragma unroll
                for (int kd = 0; kd < 2; ++kd) {
                    u32 h0, l0, h1, l1, h2, l2, h3, l3;
                    bsplit(o[2 * kd][0], o[2 * kd][1], h0, l0);
                    bsplit(o[2 * kd][2], o[2 * kd][3], h1, l1);
                    bsplit(o[2 * kd + 1][0], o[2 * kd + 1][1], h2, l2);
                    bsplit(o[2 * kd + 1][2], o[2 * kd + 1][3], h3, l3);
                    const int off = ((2 * h + kd) * 4 + t) * 32 + lane;
                    aoH[off] = make_uint4(h0, h1, h2, h3);
                    aoL[off] = make_uint4(l0, l1, l2, l3);
                }
            }
        }
        __syncthreads();   // ao ready

        // ---- P4: proj, 16 warps: warp = (m16 tile mw2, 32-col group nw2) ----
        {
            const int mw2 = warp & 3;
            const int nw2 = warp >> 2;
            const u32* aoH = (const u32*)(smem + SM_QF_H);
            const u32* aoL = (const u32*)(smem + SM_QF_L);
            const uint4* pw4 = (const uint4*)(smem + SM_PW4);

            float c[4][4];
            #pragma unroll
            for (int j = 0; j < 4; ++j)
                #pragma unroll
                for (int q = 0; q < 4; ++q) c[j][q] = 0.f;

            #pragma unroll
            for (int k16 = 0; k16 < 8; ++k16) {
                u32 aH[4], aL[4];
                uint4 vh = *(const uint4*)&aoH[((k16 * 4 + mw2) * 32 + lane) * 4];
                uint4 vl = *(const uint4*)&aoL[((k16 * 4 + mw2) * 32 + lane) * 4];
                aH[0] = vh.x; aH[1] = vh.y; aH[2] = vh.z; aH[3] = vh.w;
                aL[0] = vl.x; aL[1] = vl.y; aL[2] = vl.z; aL[3] = vl.w;
                #pragma unroll
                for (int j = 0; j < 4; ++j) {
                    uint4 wv = pw4[(k16 * 16 + nw2 * 4 + j) * 32 + lane];
                    u32 bH[2] = {wv.x, wv.y};
                    u32 bL[2] = {wv.z, wv.w};
                    mma_bf16(c[j], aH, bH);
                    mma_bf16(c[j], aH, bL);
                    mma_bf16(c[j], aL, bH);
                }
            }

            float* ob = out + (size_t)b * (N_TOK * CDIM);
            const int r0 = mw2 * 16 + g;
            const int r1 = r0 + 8;
            #pragma unroll
            for (int j = 0; j < 4; ++j) {
                const int col = nw2 * 32 + j * 8 + 2 * tig;
                const float b0 = proj_b[col], b1 = proj_b[col + 1];
                if (r0 < N_TOK)
                    *(float2*)&ob[r0 * CDIM + col] = make_float2(c[j][0] + b0, c[j][1] + b1);
                if (r1 < N_TOK)
                    *(float2*)&ob[r1 * CDIM + col] = make_float2(c[j][2] + b0, c[j][3] + b1);
            }
        }
    }
}

extern "C" void kernel_launch(void* const* d_in, const int* in_sizes, int n_in,
                              void* d_out, int out_size)
{
    const float* x          = (const float*)d_in[0];
    const float* mask       = (const float*)d_in[1];
    const float* qkv_w      = (const float*)d_in[2];
    const float* qkv_b      = (const float*)d_in[3];
    const float* proj_w     = (const float*)d_in[4];
    const float* proj_b     = (const float*)d_in[5];
    const float* bias_table = (const float*)d_in[6];
    const int*   rel_index  = (const int*)d_in[7];
    float* out = (float*)d_out;

    const int B = in_sizes[0] / (N_TOK * CDIM);

    {
        const int TOT = NWIN * NH * 4 * 8 * 32 * 4;
        build_abias_kernel<<<(TOT + 255) / 256, 256>>>(mask, bias_table, rel_index);
    }
    {
        uint4* d4;
        cudaGetSymbolAddress((void**)&d4, g_wqkv4);
        pack_w4_kernel<<<(8 * 48 * 32 + 255) / 256, 256>>>(qkv_w, d4, QKV_N, 48, 8 * 48 * 32);
        cudaGetSymbolAddress((void**)&d4, g_wproj4);
        pack_w4_kernel<<<(8 * 16 * 32 + 255) / 256, 256>>>(proj_w, d4, CDIM, 16, 8 * 16 * 32);
    }

    const int grid = (B < NBLOCKS) ? B : NBLOCKS;
    cudaFuncSetAttribute(win_attn_kernel,
                         cudaFuncAttributeMaxDynamicSharedMemorySize, SMEM_BYTES);
    win_attn_kernel<<<grid, NTHREADS, SMEM_BYTES>>>(x, qkv_b, proj_b, out, B);
}